// round 15
// baseline (speedup 1.0000x reference)
#include <cuda_runtime.h>
#include <cuda_bf16.h>
#include <cstdint>
#include <math.h>

typedef unsigned long long ull;

// Problem constants (fixed by the dataset)
#define N_NODES 25000
#define N_EDGES 400000
#define IN_FEATS 256
#define HID 64
#define HEADS 8
#define HF (HID*HEADS)      // 512
#define CLASSES 32

// ---------------- scratch (static __device__ — no allocs allowed) ----------
__device__ float g_z [N_NODES * HF];
__device__ float g_x1[N_NODES * HF];
__device__ float g_x2[N_NODES * HF];
__device__ float g_el[N_NODES * HEADS];
__device__ float g_er[N_NODES * HEADS];
__device__ int   g_rowptr[N_NODES + 1];

// ---------------- small PTX helpers ---------------------------------------
__device__ __forceinline__ uint32_t smem_u32(const void* p) {
    uint32_t a;
    asm("{ .reg .u64 t; cvta.to.shared.u64 t, %1; cvt.u32.u64 %0, t; }" : "=r"(a) : "l"(p));
    return a;
}
__device__ __forceinline__ void ldm_x4(uint32_t* r, uint32_t addr) {
    asm volatile("ldmatrix.sync.aligned.m8n8.x4.shared.b16 {%0,%1,%2,%3}, [%4];"
        : "=r"(r[0]), "=r"(r[1]), "=r"(r[2]), "=r"(r[3]) : "r"(addr));
}
__device__ __forceinline__ void mma_bf16(float* c, const uint32_t* a, const uint32_t* b) {
    asm volatile(
        "mma.sync.aligned.m16n8k16.row.col.f32.bf16.bf16.f32 "
        "{%0,%1,%2,%3}, {%4,%5,%6,%7}, {%8,%9}, {%0,%1,%2,%3};"
        : "+f"(c[0]), "+f"(c[1]), "+f"(c[2]), "+f"(c[3])
        : "r"(a[0]), "r"(a[1]), "r"(a[2]), "r"(a[3]), "r"(b[0]), "r"(b[1]));
}

// packed f32x2 helpers (aggregate kernel)
__device__ __forceinline__ ull dup_f32x2(float b) {
    ull r; asm("mov.b64 %0, {%1, %1};" : "=l"(r) : "r"(__float_as_uint(b))); return r;
}
__device__ __forceinline__ void ffma2(ull& d, ull a, ull b) {
    asm("fma.rn.f32x2 %0, %1, %2, %0;" : "+l"(d) : "l"(a), "l"(b));
}
__device__ __forceinline__ float2 unpack_f32x2(ull v) {
    float2 p; asm("mov.b64 {%0, %1}, %2;" : "=f"(p.x), "=f"(p.y) : "l"(v)); return p;
}

// ---------------- CSR row offsets from sorted dst --------------------------
__global__ void rowptr_kernel(const int* __restrict__ dst, int* __restrict__ rowptr,
                              int E, int N) {
    int v = blockIdx.x * blockDim.x + threadIdx.x;
    if (v > N) return;
    int lo = 0, hi = E;
    while (lo < hi) {
        int mid = (lo + hi) >> 1;
        if (dst[mid] < v) lo = mid + 1; else hi = mid;
    }
    rowptr[v] = lo;
}

// =================== bf16-split mma.sync GEMM: C = A[M,K]*B[N,K]^T =========
// a = hi + res, both bf16.  C += hi*hi + hi*res + res*hi  (error ~2^-17).
// Mainloop EXACT round-13 structure (measured 400us total).
// FUSE: CTA's N-tile covers one complete attention group (BN==F) -> compute
// el/er in the epilogue from register accumulators. HOUT = heads in output.
template <int BN, int WM, int WN, bool FUSE, int HOUT>
__global__ void __launch_bounds__(256, 2)
gemm_mma_kernel(const float* __restrict__ A, const float* __restrict__ B,
                float* __restrict__ C, int M, int N, int K,
                const float* __restrict__ alv, const float* __restrict__ arv,
                float* __restrict__ elv, float* __restrict__ erv) {
    constexpr int BM = 128, BK = 32, ROWP = 40;   // 40 bf16 = 80B row stride
    constexpr int WTM = BM / WM;
    constexpr int WTN = BN / WN;
    constexpr int MSUB = WTM / 16;
    constexpr int NSUB = WTN / 8;
    constexpr int BQ = (BN * BK / 4) / 256;       // float4 B loads per thread

    __shared__ __align__(16) __nv_bfloat16 Ah[BM * ROWP];
    __shared__ __align__(16) __nv_bfloat16 Ar[BM * ROWP];
    __shared__ __align__(16) __nv_bfloat16 Bh[BN * ROWP];
    __shared__ __align__(16) __nv_bfloat16 Br[BN * ROWP];
    __shared__ float sEl[WN][BM];
    __shared__ float sEr[WN][BM];

    const int tid = threadIdx.x, wid = tid >> 5, lane = tid & 31;
    const int m0 = blockIdx.y * BM, n0 = blockIdx.x * BN;
    const int wm = wid % WM, wn = wid / WM;
    const int wmb = wm * WTM, wnb = wn * WTN;

    float acc[MSUB][NSUB][4];
#pragma unroll
    for (int i = 0; i < MSUB; ++i)
#pragma unroll
        for (int j = 0; j < NSUB; ++j)
#pragma unroll
            for (int q = 0; q < 4; ++q) acc[i][j][q] = 0.f;

    float4 aS[4], bS[BQ > 0 ? BQ : 1];

    auto loadA = [&](int c) {
        const int k0 = c * BK;
#pragma unroll
        for (int it = 0; it < 4; ++it) {
            int idx = tid + it * 256;
            int row = idx >> 3, col = (idx & 7) * 4;
            int m = m0 + row;
            aS[it] = (m < M) ? *(const float4*)(A + (size_t)m * K + k0 + col)
                             : make_float4(0.f, 0.f, 0.f, 0.f);
        }
    };
    auto loadB = [&](int c) {
        const int k0 = c * BK;
#pragma unroll
        for (int it = 0; it < BQ; ++it) {
            int idx = tid + it * 256;
            int row = idx >> 3, col = (idx & 7) * 4;
            bS[it] = *(const float4*)(B + (size_t)(n0 + row) * K + k0 + col);
        }
    };
    auto cvt_store = [&](__nv_bfloat16* Sh, __nv_bfloat16* Sr, int idx, float4 v) {
        int row = idx >> 3, col = (idx & 7) * 4;
        float hx = __bfloat162float(__float2bfloat16_rn(v.x));
        float hy = __bfloat162float(__float2bfloat16_rn(v.y));
        float hz = __bfloat162float(__float2bfloat16_rn(v.z));
        float hw = __bfloat162float(__float2bfloat16_rn(v.w));
        __nv_bfloat162 h01 = __floats2bfloat162_rn(hx, hy);
        __nv_bfloat162 h23 = __floats2bfloat162_rn(hz, hw);
        __nv_bfloat162 r01 = __floats2bfloat162_rn(v.x - hx, v.y - hy);
        __nv_bfloat162 r23 = __floats2bfloat162_rn(v.z - hz, v.w - hw);
        *reinterpret_cast<__nv_bfloat162*>(&Sh[row * ROWP + col])     = h01;
        *reinterpret_cast<__nv_bfloat162*>(&Sh[row * ROWP + col + 2]) = h23;
        *reinterpret_cast<__nv_bfloat162*>(&Sr[row * ROWP + col])     = r01;
        *reinterpret_cast<__nv_bfloat162*>(&Sr[row * ROWP + col + 2]) = r23;
    };
    auto storeA = [&]() {
#pragma unroll
        for (int it = 0; it < 4; ++it) cvt_store(Ah, Ar, tid + it * 256, aS[it]);
    };
    auto storeB = [&]() {
#pragma unroll
        for (int it = 0; it < BQ; ++it) cvt_store(Bh, Br, tid + it * 256, bS[it]);
    };

    const uint32_t ahBase = smem_u32(Ah), arBase = smem_u32(Ar);
    const uint32_t bhBase = smem_u32(Bh), brBase = smem_u32(Br);

    const int NCH = K / BK;
    loadA(0); loadB(0);
    storeA(); storeB();

    for (int c = 0; c < NCH; ++c) {
        __syncthreads();
        if (c + 1 < NCH) { loadA(c + 1); loadB(c + 1); }

#pragma unroll
        for (int ks = 0; ks < 2; ++ks) {
            const int k0 = ks * 16;
            uint32_t afh[MSUB][4], afr[MSUB][4];
            const int acol = k0 + ((lane >> 4) << 3);
#pragma unroll
            for (int ms = 0; ms < MSUB; ++ms) {
                uint32_t off = (uint32_t)((wmb + ms * 16 + (lane & 15)) * ROWP + acol) * 2;
                ldm_x4(afh[ms], ahBase + off);
                ldm_x4(afr[ms], arBase + off);
            }
            uint32_t bfh[NSUB][2], bfr[NSUB][2];
            const int bro = ((lane & 16) >> 1) + (lane & 7);
            const int bcol = k0 + (lane & 8);
#pragma unroll
            for (int np = 0; np < NSUB / 2; ++np) {
                uint32_t off = (uint32_t)((wnb + np * 16 + bro) * ROWP + bcol) * 2;
                uint32_t t4[4];
                ldm_x4(t4, bhBase + off);
                bfh[2 * np][0] = t4[0]; bfh[2 * np][1] = t4[1];
                bfh[2 * np + 1][0] = t4[2]; bfh[2 * np + 1][1] = t4[3];
                ldm_x4(t4, brBase + off);
                bfr[2 * np][0] = t4[0]; bfr[2 * np][1] = t4[1];
                bfr[2 * np + 1][0] = t4[2]; bfr[2 * np + 1][1] = t4[3];
            }
#pragma unroll
            for (int ms = 0; ms < MSUB; ++ms)
#pragma unroll
                for (int ns = 0; ns < NSUB; ++ns) {
                    mma_bf16(acc[ms][ns], afh[ms], bfh[ns]);
                    mma_bf16(acc[ms][ns], afh[ms], bfr[ns]);
                    mma_bf16(acc[ms][ns], afr[ms], bfh[ns]);
                }
        }
        __syncthreads();
        if (c + 1 < NCH) { storeA(); storeB(); }
    }

    // epilogue: write C tile
    const int g = lane >> 2, t = lane & 3;
#pragma unroll
    for (int ms = 0; ms < MSUB; ++ms)
#pragma unroll
        for (int ns = 0; ns < NSUB; ++ns) {
            int m = m0 + wmb + ms * 16 + g;
            int n = n0 + wnb + ns * 8 + 2 * t;
            if (m < M)
                *(float2*)(C + (size_t)m * N + n) = make_float2(acc[ms][ns][0], acc[ms][ns][1]);
            if (m + 8 < M)
                *(float2*)(C + (size_t)(m + 8) * N + n) = make_float2(acc[ms][ns][2], acc[ms][ns][3]);
        }

    // fused el/er: this CTA's N-tile == attention group n0/BN; reduce from regs.
    if constexpr (FUSE) {
        const float* alh = alv + n0;
        const float* arh = arv + n0;
        float sl[MSUB][2], sr[MSUB][2];
#pragma unroll
        for (int ms = 0; ms < MSUB; ++ms) {
            sl[ms][0] = sl[ms][1] = 0.f;
            sr[ms][0] = sr[ms][1] = 0.f;
        }
#pragma unroll
        for (int ns = 0; ns < NSUB; ++ns) {
            int j = wnb + ns * 8 + 2 * t;
            float a0 = alh[j], a1 = alh[j + 1];
            float b0 = arh[j], b1 = arh[j + 1];
#pragma unroll
            for (int ms = 0; ms < MSUB; ++ms) {
                sl[ms][0] += acc[ms][ns][0] * a0 + acc[ms][ns][1] * a1;
                sl[ms][1] += acc[ms][ns][2] * a0 + acc[ms][ns][3] * a1;
                sr[ms][0] += acc[ms][ns][0] * b0 + acc[ms][ns][1] * b1;
                sr[ms][1] += acc[ms][ns][2] * b0 + acc[ms][ns][3] * b1;
            }
        }
        // reduce over t (4 lanes of a quad share the same rows)
#pragma unroll
        for (int off = 1; off <= 2; off <<= 1)
#pragma unroll
            for (int ms = 0; ms < MSUB; ++ms) {
                sl[ms][0] += __shfl_xor_sync(0xFFFFFFFFu, sl[ms][0], off);
                sl[ms][1] += __shfl_xor_sync(0xFFFFFFFFu, sl[ms][1], off);
                sr[ms][0] += __shfl_xor_sync(0xFFFFFFFFu, sr[ms][0], off);
                sr[ms][1] += __shfl_xor_sync(0xFFFFFFFFu, sr[ms][1], off);
            }
        if (t == 0) {
#pragma unroll
            for (int ms = 0; ms < MSUB; ++ms) {
                int r = wmb + ms * 16 + g;
                sEl[wn][r]     = sl[ms][0];
                sEl[wn][r + 8] = sl[ms][1];
                sEr[wn][r]     = sr[ms][0];
                sEr[wn][r + 8] = sr[ms][1];
            }
        }
        __syncthreads();
        if (tid < BM) {
            int m = m0 + tid;
            if (m < M) {
                float e1 = sEl[0][tid], e2 = sEr[0][tid];
#pragma unroll
                for (int w = 1; w < WN; ++w) { e1 += sEl[w][tid]; e2 += sEr[w][tid]; }
                int hh = n0 / BN;            // group index within HOUT
                elv[(size_t)m * HOUT + hh] = e1;
                erv[(size_t)m * HOUT + hh] = e2;
            }
        }
    }
}

// ---------------- per-node edge softmax + aggregation (one warp per node) --
// Round-10 structure, WITHOUT the max pass: exp(e)/sum(exp(e)) is identical
// to the max-subtracted softmax (e is O(1) here, no overflow risk).
template <int H, int F, bool ELU>
__global__ void aggregate_kernel(const float* __restrict__ z,
                                 const int* __restrict__ src,
                                 const int* __restrict__ rowptr,
                                 const float* __restrict__ el,
                                 const float* __restrict__ er,
                                 float* __restrict__ out, int N) {
    constexpr int HFv = H * F;
    int warp_id = (blockIdx.x * blockDim.x + threadIdx.x) >> 5;
    if (warp_id >= N) return;
    int lane = threadIdx.x & 31;
    int v = warp_id;
    int start = rowptr[v];
    int end   = rowptr[v + 1];

    int h = lane % H;
    float erv = er[(size_t)v * H + h];

    float denom = 0.f;

    if constexpr (HFv >= 64 && F == 64 && H == 8) {
        constexpr int KP = HFv / 64;   // 8 pair-chunks of 64 floats, chunk k = head k
        ull acc[KP];
#pragma unroll
        for (int k = 0; k < KP; ++k) acc[k] = 0ull;

        int i = start;
        for (; i + 2 <= end; i += 2) {
            int a0 = 0, a1 = 0;
            if (lane == 0) { a0 = src[i]; a1 = src[i + 1]; }
            int s0 = __shfl_sync(0xFFFFFFFFu, a0, 0);
            int s1 = __shfl_sync(0xFFFFFFFFu, a1, 0);
            float e0 = el[(size_t)s0 * H + h] + erv;
            float e1 = el[(size_t)s1 * H + h] + erv;
            e0 = e0 > 0.f ? e0 : 0.2f * e0;
            e1 = e1 > 0.f ? e1 : 0.2f * e1;
            float w0 = __expf(e0);
            float w1 = __expf(e1);
            denom += w0 + w1;
            const float* z0 = z + (size_t)s0 * HFv;
            const float* z1 = z + (size_t)s1 * HFv;
#pragma unroll
            for (int k = 0; k < KP; ++k) {
                float wk0 = __shfl_sync(0xFFFFFFFFu, w0, k);
                float wk1 = __shfl_sync(0xFFFFFFFFu, w1, k);
                ull zv0 = *(const ull*)(z0 + k * 64 + lane * 2);
                ull zv1 = *(const ull*)(z1 + k * 64 + lane * 2);
                ffma2(acc[k], zv0, dup_f32x2(wk0));
                ffma2(acc[k], zv1, dup_f32x2(wk1));
            }
        }
        if (i < end) {
            int a0 = 0;
            if (lane == 0) a0 = src[i];
            int s0 = __shfl_sync(0xFFFFFFFFu, a0, 0);
            float e0 = el[(size_t)s0 * H + h] + erv;
            e0 = e0 > 0.f ? e0 : 0.2f * e0;
            float w0 = __expf(e0);
            denom += w0;
            const float* z0 = z + (size_t)s0 * HFv;
#pragma unroll
            for (int k = 0; k < KP; ++k) {
                float wk0 = __shfl_sync(0xFFFFFFFFu, w0, k);
                ull zv0 = *(const ull*)(z0 + k * 64 + lane * 2);
                ffma2(acc[k], zv0, dup_f32x2(wk0));
            }
        }

        float* outr = out + (size_t)v * HFv;
#pragma unroll
        for (int k = 0; k < KP; ++k) {
            float d = __shfl_sync(0xFFFFFFFFu, denom, k);
            float2 p = unpack_f32x2(acc[k]);
            float vx = (end > start) ? p.x / d : 0.f;
            float vy = (end > start) ? p.y / d : 0.f;
            if (ELU) {
                vx = vx > 0.f ? vx : (__expf(vx) - 1.f);
                vy = vy > 0.f ? vy : (__expf(vy) - 1.f);
            }
            *(float2*)(outr + k * 64 + lane * 2) = make_float2(vx, vy);
        }
    } else {
        constexpr int KF = HFv / 32;
        float acc[KF];
#pragma unroll
        for (int k = 0; k < KF; ++k) acc[k] = 0.f;

        for (int i = start; i < end; ++i) {
            int a0 = 0;
            if (lane == 0) a0 = src[i];
            int s = __shfl_sync(0xFFFFFFFFu, a0, 0);
            float e = el[(size_t)s * H + h] + erv;
            e = e > 0.f ? e : 0.2f * e;
            float w = __expf(e);
            denom += w;
            float wv[H];
#pragma unroll
            for (int hh = 0; hh < H; ++hh) wv[hh] = __shfl_sync(0xFFFFFFFFu, w, hh);
            const float* zr = z + (size_t)s * HFv;
#pragma unroll
            for (int k = 0; k < KF; ++k)
                acc[k] += wv[(k * 32) / F] * zr[k * 32 + lane];
        }

        float denv[H];
#pragma unroll
        for (int hh = 0; hh < H; ++hh) denv[hh] = __shfl_sync(0xFFFFFFFFu, denom, hh);

        float* outr = out + (size_t)v * HFv;
#pragma unroll
        for (int k = 0; k < KF; ++k) {
            float d = denv[(k * 32) / F];
            float val = (end > start) ? acc[k] / d : 0.f;
            if (ELU) val = val > 0.f ? val : (__expf(val) - 1.f);
            outr[k * 32 + lane] = val;
        }
    }
}

// ---------------- launch --------------------------------------------------
extern "C" void kernel_launch(void* const* d_in, const int* in_sizes, int n_in,
                              void* d_out, int out_size) {
    const float* h   = (const float*)d_in[0];
    const int*   src = (const int*)  d_in[1];
    const int*   dst = (const int*)  d_in[2];
    const float* W1  = (const float*)d_in[3];
    const float* al1 = (const float*)d_in[4];
    const float* ar1 = (const float*)d_in[5];
    const float* W2  = (const float*)d_in[6];
    const float* al2 = (const float*)d_in[7];
    const float* ar2 = (const float*)d_in[8];
    const float* W3  = (const float*)d_in[9];
    const float* al3 = (const float*)d_in[10];
    const float* ar3 = (const float*)d_in[11];
    float* out = (float*)d_out;

    const int N = N_NODES, E = N_EDGES;

    float *z, *x1, *x2, *el, *er;
    int* rowptr;
    cudaGetSymbolAddress((void**)&z,  g_z);
    cudaGetSymbolAddress((void**)&x1, g_x1);
    cudaGetSymbolAddress((void**)&x2, g_x2);
    cudaGetSymbolAddress((void**)&el, g_el);
    cudaGetSymbolAddress((void**)&er, g_er);
    cudaGetSymbolAddress((void**)&rowptr, g_rowptr);

    rowptr_kernel<<<(N + 1 + 255) / 256, 256>>>(dst, rowptr, E, N);

    const int mtiles = (N + 127) / 128;          // 196
    int agg_blocks = (N * 32 + 255) / 256;

    // ---- layer 1: z = h @ W1^T  [N,256] -> [N,512], el/er fused
    gemm_mma_kernel<64, 4, 2, true, HEADS><<<dim3(HF / 64, mtiles), 256>>>(
        h, W1, z, N, HF, IN_FEATS, al1, ar1, el, er);
    aggregate_kernel<HEADS, HID, true><<<agg_blocks, 256>>>(z, src, rowptr, el, er, x1, N);

    // ---- layer 2: z = x1 @ W2^T  [N,512] -> [N,512], el/er fused
    gemm_mma_kernel<64, 4, 2, true, HEADS><<<dim3(HF / 64, mtiles), 256>>>(
        x1, W2, z, N, HF, HF, al2, ar2, el, er);
    aggregate_kernel<HEADS, HID, true><<<agg_blocks, 256>>>(z, src, rowptr, el, er, x2, N);

    // ---- layer 3: z = x2 @ W3^T  [N,512] -> [N,32], el/er fused (H=1)
    gemm_mma_kernel<32, 8, 1, true, 1><<<dim3(1, mtiles), 256>>>(
        x2, W3, z, N, CLASSES, HF, al3, ar3, el, er);
    aggregate_kernel<1, CLASSES, false><<<agg_blocks, 256>>>(z, src, rowptr, el, er, out, N);
}

// round 16
// speedup vs baseline: 1.4947x; 1.4947x over previous
#include <cuda_runtime.h>
#include <cuda_bf16.h>
#include <cstdint>
#include <math.h>

typedef unsigned long long ull;

// Problem constants (fixed by the dataset)
#define N_NODES 25000
#define N_EDGES 400000
#define IN_FEATS 256
#define HID 64
#define HEADS 8
#define HF (HID*HEADS)      // 512
#define CLASSES 32

// ---------------- scratch (static __device__ — no allocs allowed) ----------
__device__ float g_z [N_NODES * HF];
__device__ float g_x1[N_NODES * HF];
__device__ float g_x2[N_NODES * HF];
__device__ float g_el[N_NODES * HEADS];
__device__ float g_er[N_NODES * HEADS];
__device__ int   g_rowptr[N_NODES + 1];

// ---------------- small PTX helpers ---------------------------------------
__device__ __forceinline__ uint32_t smem_u32(const void* p) {
    uint32_t a;
    asm("{ .reg .u64 t; cvta.to.shared.u64 t, %1; cvt.u32.u64 %0, t; }" : "=r"(a) : "l"(p));
    return a;
}
__device__ __forceinline__ void ldm_x4(uint32_t* r, uint32_t addr) {
    asm volatile("ldmatrix.sync.aligned.m8n8.x4.shared.b16 {%0,%1,%2,%3}, [%4];"
        : "=r"(r[0]), "=r"(r[1]), "=r"(r[2]), "=r"(r[3]) : "r"(addr));
}
__device__ __forceinline__ void mma_bf16(float* c, const uint32_t* a, const uint32_t* b) {
    asm volatile(
        "mma.sync.aligned.m16n8k16.row.col.f32.bf16.bf16.f32 "
        "{%0,%1,%2,%3}, {%4,%5,%6,%7}, {%8,%9}, {%0,%1,%2,%3};"
        : "+f"(c[0]), "+f"(c[1]), "+f"(c[2]), "+f"(c[3])
        : "r"(a[0]), "r"(a[1]), "r"(a[2]), "r"(a[3]), "r"(b[0]), "r"(b[1]));
}

// packed f32x2 helpers (aggregate kernel)
__device__ __forceinline__ ull dup_f32x2(float b) {
    ull r; asm("mov.b64 %0, {%1, %1};" : "=l"(r) : "r"(__float_as_uint(b))); return r;
}
__device__ __forceinline__ void ffma2(ull& d, ull a, ull b) {
    asm("fma.rn.f32x2 %0, %1, %2, %0;" : "+l"(d) : "l"(a), "l"(b));
}
__device__ __forceinline__ float2 unpack_f32x2(ull v) {
    float2 p; asm("mov.b64 {%0, %1}, %2;" : "=f"(p.x), "=f"(p.y) : "l"(v)); return p;
}

// ---------------- CSR row offsets from sorted dst --------------------------
__global__ void rowptr_kernel(const int* __restrict__ dst, int* __restrict__ rowptr,
                              int E, int N) {
    int v = blockIdx.x * blockDim.x + threadIdx.x;
    if (v > N) return;
    int lo = 0, hi = E;
    while (lo < hi) {
        int mid = (lo + hi) >> 1;
        if (dst[mid] < v) lo = mid + 1; else hi = mid;
    }
    rowptr[v] = lo;
}

// =================== bf16-split mma.sync GEMM: C = A[M,K]*B[N,K]^T =========
// a = hi + res, both bf16.  C += hi*hi + hi*res + res*hi  (error ~2^-17).
// Mainloop EXACT round-13 structure (measured 400us total).
// FUSE: CTA's N-tile covers one complete attention group (BN==F) -> compute
// el/er in the epilogue from register accumulators. HOUT = heads in output.
template <int BN, int WM, int WN, bool FUSE, int HOUT>
__global__ void __launch_bounds__(256, 2)
gemm_mma_kernel(const float* __restrict__ A, const float* __restrict__ B,
                float* __restrict__ C, int M, int N, int K,
                const float* __restrict__ alv, const float* __restrict__ arv,
                float* __restrict__ elv, float* __restrict__ erv) {
    constexpr int BM = 128, BK = 32, ROWP = 40;   // 40 bf16 = 80B row stride
    constexpr int WTM = BM / WM;
    constexpr int WTN = BN / WN;
    constexpr int MSUB = WTM / 16;
    constexpr int NSUB = WTN / 8;
    constexpr int BQ = (BN * BK / 4) / 256;       // float4 B loads per thread

    __shared__ __align__(16) __nv_bfloat16 Ah[BM * ROWP];
    __shared__ __align__(16) __nv_bfloat16 Ar[BM * ROWP];
    __shared__ __align__(16) __nv_bfloat16 Bh[BN * ROWP];
    __shared__ __align__(16) __nv_bfloat16 Br[BN * ROWP];
    __shared__ float sEl[WN][BM];
    __shared__ float sEr[WN][BM];

    const int tid = threadIdx.x, wid = tid >> 5, lane = tid & 31;
    const int m0 = blockIdx.y * BM, n0 = blockIdx.x * BN;
    const int wm = wid % WM, wn = wid / WM;
    const int wmb = wm * WTM, wnb = wn * WTN;

    float acc[MSUB][NSUB][4];
#pragma unroll
    for (int i = 0; i < MSUB; ++i)
#pragma unroll
        for (int j = 0; j < NSUB; ++j)
#pragma unroll
            for (int q = 0; q < 4; ++q) acc[i][j][q] = 0.f;

    float4 aS[4], bS[BQ > 0 ? BQ : 1];

    auto loadA = [&](int c) {
        const int k0 = c * BK;
#pragma unroll
        for (int it = 0; it < 4; ++it) {
            int idx = tid + it * 256;
            int row = idx >> 3, col = (idx & 7) * 4;
            int m = m0 + row;
            aS[it] = (m < M) ? *(const float4*)(A + (size_t)m * K + k0 + col)
                             : make_float4(0.f, 0.f, 0.f, 0.f);
        }
    };
    auto loadB = [&](int c) {
        const int k0 = c * BK;
#pragma unroll
        for (int it = 0; it < BQ; ++it) {
            int idx = tid + it * 256;
            int row = idx >> 3, col = (idx & 7) * 4;
            bS[it] = *(const float4*)(B + (size_t)(n0 + row) * K + k0 + col);
        }
    };
    auto cvt_store = [&](__nv_bfloat16* Sh, __nv_bfloat16* Sr, int idx, float4 v) {
        int row = idx >> 3, col = (idx & 7) * 4;
        float hx = __bfloat162float(__float2bfloat16_rn(v.x));
        float hy = __bfloat162float(__float2bfloat16_rn(v.y));
        float hz = __bfloat162float(__float2bfloat16_rn(v.z));
        float hw = __bfloat162float(__float2bfloat16_rn(v.w));
        __nv_bfloat162 h01 = __floats2bfloat162_rn(hx, hy);
        __nv_bfloat162 h23 = __floats2bfloat162_rn(hz, hw);
        __nv_bfloat162 r01 = __floats2bfloat162_rn(v.x - hx, v.y - hy);
        __nv_bfloat162 r23 = __floats2bfloat162_rn(v.z - hz, v.w - hw);
        *reinterpret_cast<__nv_bfloat162*>(&Sh[row * ROWP + col])     = h01;
        *reinterpret_cast<__nv_bfloat162*>(&Sh[row * ROWP + col + 2]) = h23;
        *reinterpret_cast<__nv_bfloat162*>(&Sr[row * ROWP + col])     = r01;
        *reinterpret_cast<__nv_bfloat162*>(&Sr[row * ROWP + col + 2]) = r23;
    };
    auto storeA = [&]() {
#pragma unroll
        for (int it = 0; it < 4; ++it) cvt_store(Ah, Ar, tid + it * 256, aS[it]);
    };
    auto storeB = [&]() {
#pragma unroll
        for (int it = 0; it < BQ; ++it) cvt_store(Bh, Br, tid + it * 256, bS[it]);
    };

    const uint32_t ahBase = smem_u32(Ah), arBase = smem_u32(Ar);
    const uint32_t bhBase = smem_u32(Bh), brBase = smem_u32(Br);

    const int NCH = K / BK;
    loadA(0); loadB(0);
    storeA(); storeB();

    for (int c = 0; c < NCH; ++c) {
        __syncthreads();
        if (c + 1 < NCH) { loadA(c + 1); loadB(c + 1); }

#pragma unroll
        for (int ks = 0; ks < 2; ++ks) {
            const int k0 = ks * 16;
            uint32_t afh[MSUB][4], afr[MSUB][4];
            const int acol = k0 + ((lane >> 4) << 3);
#pragma unroll
            for (int ms = 0; ms < MSUB; ++ms) {
                uint32_t off = (uint32_t)((wmb + ms * 16 + (lane & 15)) * ROWP + acol) * 2;
                ldm_x4(afh[ms], ahBase + off);
                ldm_x4(afr[ms], arBase + off);
            }
            uint32_t bfh[NSUB][2], bfr[NSUB][2];
            const int bro = ((lane & 16) >> 1) + (lane & 7);
            const int bcol = k0 + (lane & 8);
#pragma unroll
            for (int np = 0; np < NSUB / 2; ++np) {
                uint32_t off = (uint32_t)((wnb + np * 16 + bro) * ROWP + bcol) * 2;
                uint32_t t4[4];
                ldm_x4(t4, bhBase + off);
                bfh[2 * np][0] = t4[0]; bfh[2 * np][1] = t4[1];
                bfh[2 * np + 1][0] = t4[2]; bfh[2 * np + 1][1] = t4[3];
                ldm_x4(t4, brBase + off);
                bfr[2 * np][0] = t4[0]; bfr[2 * np][1] = t4[1];
                bfr[2 * np + 1][0] = t4[2]; bfr[2 * np + 1][1] = t4[3];
            }
#pragma unroll
            for (int ms = 0; ms < MSUB; ++ms)
#pragma unroll
                for (int ns = 0; ns < NSUB; ++ns) {
                    mma_bf16(acc[ms][ns], afh[ms], bfh[ns]);
                    mma_bf16(acc[ms][ns], afh[ms], bfr[ns]);
                    mma_bf16(acc[ms][ns], afr[ms], bfh[ns]);
                }
        }
        __syncthreads();
        if (c + 1 < NCH) { storeA(); storeB(); }
    }

    // epilogue: write C tile
    const int g = lane >> 2, t = lane & 3;
#pragma unroll
    for (int ms = 0; ms < MSUB; ++ms)
#pragma unroll
        for (int ns = 0; ns < NSUB; ++ns) {
            int m = m0 + wmb + ms * 16 + g;
            int n = n0 + wnb + ns * 8 + 2 * t;
            if (m < M)
                *(float2*)(C + (size_t)m * N + n) = make_float2(acc[ms][ns][0], acc[ms][ns][1]);
            if (m + 8 < M)
                *(float2*)(C + (size_t)(m + 8) * N + n) = make_float2(acc[ms][ns][2], acc[ms][ns][3]);
        }

    // fused el/er: this CTA's N-tile == attention group n0/BN; reduce from regs.
    if constexpr (FUSE) {
        const float* alh = alv + n0;
        const float* arh = arv + n0;
        float sl[MSUB][2], sr[MSUB][2];
#pragma unroll
        for (int ms = 0; ms < MSUB; ++ms) {
            sl[ms][0] = sl[ms][1] = 0.f;
            sr[ms][0] = sr[ms][1] = 0.f;
        }
#pragma unroll
        for (int ns = 0; ns < NSUB; ++ns) {
            int j = wnb + ns * 8 + 2 * t;
            float a0 = alh[j], a1 = alh[j + 1];
            float b0 = arh[j], b1 = arh[j + 1];
#pragma unroll
            for (int ms = 0; ms < MSUB; ++ms) {
                sl[ms][0] += acc[ms][ns][0] * a0 + acc[ms][ns][1] * a1;
                sl[ms][1] += acc[ms][ns][2] * a0 + acc[ms][ns][3] * a1;
                sr[ms][0] += acc[ms][ns][0] * b0 + acc[ms][ns][1] * b1;
                sr[ms][1] += acc[ms][ns][2] * b0 + acc[ms][ns][3] * b1;
            }
        }
        // reduce over t (4 lanes of a quad share the same rows)
#pragma unroll
        for (int off = 1; off <= 2; off <<= 1)
#pragma unroll
            for (int ms = 0; ms < MSUB; ++ms) {
                sl[ms][0] += __shfl_xor_sync(0xFFFFFFFFu, sl[ms][0], off);
                sl[ms][1] += __shfl_xor_sync(0xFFFFFFFFu, sl[ms][1], off);
                sr[ms][0] += __shfl_xor_sync(0xFFFFFFFFu, sr[ms][0], off);
                sr[ms][1] += __shfl_xor_sync(0xFFFFFFFFu, sr[ms][1], off);
            }
        if (t == 0) {
#pragma unroll
            for (int ms = 0; ms < MSUB; ++ms) {
                int r = wmb + ms * 16 + g;
                sEl[wn][r]     = sl[ms][0];
                sEl[wn][r + 8] = sl[ms][1];
                sEr[wn][r]     = sr[ms][0];
                sEr[wn][r + 8] = sr[ms][1];
            }
        }
        __syncthreads();
        if (tid < BM) {
            int m = m0 + tid;
            if (m < M) {
                float e1 = sEl[0][tid], e2 = sEr[0][tid];
#pragma unroll
                for (int w = 1; w < WN; ++w) { e1 += sEl[w][tid]; e2 += sEr[w][tid]; }
                int hh = n0 / BN;            // group index within HOUT
                elv[(size_t)m * HOUT + hh] = e1;
                erv[(size_t)m * HOUT + hh] = e2;
            }
        }
    }
}

// ---------------- per-node edge softmax + aggregation (one warp per node) --
// Round-10 structure, WITHOUT the max pass: exp(e)/sum(exp(e)) is identical
// to the max-subtracted softmax (e is O(1) here, no overflow risk).
template <int H, int F, bool ELU>
__global__ void aggregate_kernel(const float* __restrict__ z,
                                 const int* __restrict__ src,
                                 const int* __restrict__ rowptr,
                                 const float* __restrict__ el,
                                 const float* __restrict__ er,
                                 float* __restrict__ out, int N) {
    constexpr int HFv = H * F;
    int warp_id = (blockIdx.x * blockDim.x + threadIdx.x) >> 5;
    if (warp_id >= N) return;
    int lane = threadIdx.x & 31;
    int v = warp_id;
    int start = rowptr[v];
    int end   = rowptr[v + 1];

    int h = lane % H;
    float erv = er[(size_t)v * H + h];

    float denom = 0.f;

    if constexpr (HFv >= 64 && F == 64 && H == 8) {
        constexpr int KP = HFv / 64;   // 8 pair-chunks of 64 floats, chunk k = head k
        ull acc[KP];
#pragma unroll
        for (int k = 0; k < KP; ++k) acc[k] = 0ull;

        int i = start;
        for (; i + 2 <= end; i += 2) {
            int a0 = 0, a1 = 0;
            if (lane == 0) { a0 = src[i]; a1 = src[i + 1]; }
            int s0 = __shfl_sync(0xFFFFFFFFu, a0, 0);
            int s1 = __shfl_sync(0xFFFFFFFFu, a1, 0);
            float e0 = el[(size_t)s0 * H + h] + erv;
            float e1 = el[(size_t)s1 * H + h] + erv;
            e0 = e0 > 0.f ? e0 : 0.2f * e0;
            e1 = e1 > 0.f ? e1 : 0.2f * e1;
            float w0 = __expf(e0);
            float w1 = __expf(e1);
            denom += w0 + w1;
            const float* z0 = z + (size_t)s0 * HFv;
            const float* z1 = z + (size_t)s1 * HFv;
#pragma unroll
            for (int k = 0; k < KP; ++k) {
                float wk0 = __shfl_sync(0xFFFFFFFFu, w0, k);
                float wk1 = __shfl_sync(0xFFFFFFFFu, w1, k);
                ull zv0 = *(const ull*)(z0 + k * 64 + lane * 2);
                ull zv1 = *(const ull*)(z1 + k * 64 + lane * 2);
                ffma2(acc[k], zv0, dup_f32x2(wk0));
                ffma2(acc[k], zv1, dup_f32x2(wk1));
            }
        }
        if (i < end) {
            int a0 = 0;
            if (lane == 0) a0 = src[i];
            int s0 = __shfl_sync(0xFFFFFFFFu, a0, 0);
            float e0 = el[(size_t)s0 * H + h] + erv;
            e0 = e0 > 0.f ? e0 : 0.2f * e0;
            float w0 = __expf(e0);
            denom += w0;
            const float* z0 = z + (size_t)s0 * HFv;
#pragma unroll
            for (int k = 0; k < KP; ++k) {
                float wk0 = __shfl_sync(0xFFFFFFFFu, w0, k);
                ull zv0 = *(const ull*)(z0 + k * 64 + lane * 2);
                ffma2(acc[k], zv0, dup_f32x2(wk0));
            }
        }

        float* outr = out + (size_t)v * HFv;
#pragma unroll
        for (int k = 0; k < KP; ++k) {
            float d = __shfl_sync(0xFFFFFFFFu, denom, k);
            float2 p = unpack_f32x2(acc[k]);
            float vx = (end > start) ? p.x / d : 0.f;
            float vy = (end > start) ? p.y / d : 0.f;
            if (ELU) {
                vx = vx > 0.f ? vx : (__expf(vx) - 1.f);
                vy = vy > 0.f ? vy : (__expf(vy) - 1.f);
            }
            *(float2*)(outr + k * 64 + lane * 2) = make_float2(vx, vy);
        }
    } else {
        constexpr int KF = HFv / 32;
        float acc[KF];
#pragma unroll
        for (int k = 0; k < KF; ++k) acc[k] = 0.f;

        for (int i = start; i < end; ++i) {
            int a0 = 0;
            if (lane == 0) a0 = src[i];
            int s = __shfl_sync(0xFFFFFFFFu, a0, 0);
            float e = el[(size_t)s * H + h] + erv;
            e = e > 0.f ? e : 0.2f * e;
            float w = __expf(e);
            denom += w;
            float wv[H];
#pragma unroll
            for (int hh = 0; hh < H; ++hh) wv[hh] = __shfl_sync(0xFFFFFFFFu, w, hh);
            const float* zr = z + (size_t)s * HFv;
#pragma unroll
            for (int k = 0; k < KF; ++k)
                acc[k] += wv[(k * 32) / F] * zr[k * 32 + lane];
        }

        float denv[H];
#pragma unroll
        for (int hh = 0; hh < H; ++hh) denv[hh] = __shfl_sync(0xFFFFFFFFu, denom, hh);

        float* outr = out + (size_t)v * HFv;
#pragma unroll
        for (int k = 0; k < KF; ++k) {
            float d = denv[(k * 32) / F];
            float val = (end > start) ? acc[k] / d : 0.f;
            if (ELU) val = val > 0.f ? val : (__expf(val) - 1.f);
            outr[k * 32 + lane] = val;
        }
    }
}

// ---------------- launch --------------------------------------------------
extern "C" void kernel_launch(void* const* d_in, const int* in_sizes, int n_in,
                              void* d_out, int out_size) {
    const float* h   = (const float*)d_in[0];
    const int*   src = (const int*)  d_in[1];
    const int*   dst = (const int*)  d_in[2];
    const float* W1  = (const float*)d_in[3];
    const float* al1 = (const float*)d_in[4];
    const float* ar1 = (const float*)d_in[5];
    const float* W2  = (const float*)d_in[6];
    const float* al2 = (const float*)d_in[7];
    const float* ar2 = (const float*)d_in[8];
    const float* W3  = (const float*)d_in[9];
    const float* al3 = (const float*)d_in[10];
    const float* ar3 = (const float*)d_in[11];
    float* out = (float*)d_out;

    const int N = N_NODES, E = N_EDGES;

    float *z, *x1, *x2, *el, *er;
    int* rowptr;
    cudaGetSymbolAddress((void**)&z,  g_z);
    cudaGetSymbolAddress((void**)&x1, g_x1);
    cudaGetSymbolAddress((void**)&x2, g_x2);
    cudaGetSymbolAddress((void**)&el, g_el);
    cudaGetSymbolAddress((void**)&er, g_er);
    cudaGetSymbolAddress((void**)&rowptr, g_rowptr);

    rowptr_kernel<<<(N + 1 + 255) / 256, 256>>>(dst, rowptr, E, N);

    const int mtiles = (N + 127) / 128;          // 196
    int agg_blocks = (N * 32 + 255) / 256;

    // ---- layer 1: z = h @ W1^T  [N,256] -> [N,512], el/er fused
    gemm_mma_kernel<64, 4, 2, true, HEADS><<<dim3(HF / 64, mtiles), 256>>>(
        h, W1, z, N, HF, IN_FEATS, al1, ar1, el, er);
    aggregate_kernel<HEADS, HID, true><<<agg_blocks, 256>>>(z, src, rowptr, el, er, x1, N);

    // ---- layer 2: z = x1 @ W2^T  [N,512] -> [N,512], el/er fused
    gemm_mma_kernel<64, 4, 2, true, HEADS><<<dim3(HF / 64, mtiles), 256>>>(
        x1, W2, z, N, HF, HF, al2, ar2, el, er);
    aggregate_kernel<HEADS, HID, true><<<agg_blocks, 256>>>(z, src, rowptr, el, er, x2, N);

    // ---- layer 3: z = x2 @ W3^T  [N,512] -> [N,32], el/er fused (H=1)
    gemm_mma_kernel<32, 8, 1, true, 1><<<dim3(1, mtiles), 256>>>(
        x2, W3, z, N, CLASSES, HF, al3, ar3, el, er);
    aggregate_kernel<1, CLASSES, false><<<agg_blocks, 256>>>(z, src, rowptr, el, er, out, N);
}